// round 8
// baseline (speedup 1.0000x reference)
#include <cuda_runtime.h>
#include <cuda_bf16.h>

// Fused 2-layer RNN (hidden=1), S=2048, B=256, I=128.
//   xp[s,b] = x[s,b,:].W_ih0 + b_ih0 + b_hh0          (producers, HBM stream)
//   h1 = tanh(xp + h1*Whh0); h2 = tanh(h1*Wih1 + b1 + h2*Whh1)  (consumers)
//   out[b] = sigmoid(h2[S-1,b])
//
// R7 = R6 resubmit (R6 hit an infra failure, never measured) + __nanosleep
// in consumer poll loops. Producer: R1-measured shape (warp-per-row,
// lane-per-float4, 5-level shfl) at 4 CTAs/SM, one timestep per CTA.
// Consumer + chunk-counter sync proven in R5.

#define S_LEN  2048
#define B_SZ   256
#define NCONS  8
#define NPROD  2048                      // one timestep per producer CTA
#define NCTA   (NCONS + NPROD)
#define CHUNK  16
#define NCHUNK (S_LEN / CHUNK)           // 128

__device__ float    g_xp[S_LEN * B_SZ];  // [s][b]
__device__ unsigned g_cnt[NCHUNK + 2];   // per-chunk completion counters (+pad)
__device__ unsigned g_done;

__device__ __forceinline__ float tanh_fast(float x) {
    float y;
    asm("tanh.approx.f32 %0, %1;" : "=f"(y) : "f"(x));
    return y;
}
__device__ __forceinline__ unsigned ldrelax(const unsigned* p) {
    unsigned v;
    asm volatile("ld.relaxed.gpu.global.u32 %0, [%1];" : "=r"(v) : "l"(p) : "memory");
    return v;
}
__device__ __forceinline__ void fence_acq() {
    asm volatile("fence.acq_rel.gpu;" ::: "memory");
}
__device__ __forceinline__ void red_release_inc(unsigned* p) {
    asm volatile("red.release.gpu.global.add.u32 [%0], 1;" :: "l"(p) : "memory");
}
__device__ __forceinline__ float dot4(float4 a, float4 b) {
    return fmaf(a.x, b.x, fmaf(a.y, b.y, fmaf(a.z, b.z, a.w * b.w)));
}

// Pipelined recurrence step: computes h1_j and h2_{j-1}; both FFMA issue
// before both MUFU so the two tanh cycles overlap. (Numerics proven R2/R4/R5.)
#define STEP(xv) do {                    \
    float p1_ = fmaf(h1, w00, (xv));     \
    float p2_ = fmaf(h2, d1, sv);        \
    h1 = tanh_fast(p1_);                 \
    h2 = tanh_fast(p2_);                 \
    sv = fmaf(h1, a1, c1);               \
} while (0)

__global__ __launch_bounds__(256, 4) void rnn_fused(
    const float* __restrict__ x,
    const float* __restrict__ w_ih0,
    const float* __restrict__ w_hh0,
    const float* __restrict__ b_ih0,
    const float* __restrict__ b_hh0,
    const float* __restrict__ w_ih1,
    const float* __restrict__ w_hh1,
    const float* __restrict__ b_ih1,
    const float* __restrict__ b_hh1,
    float* __restrict__ out)
{
    const int cta = blockIdx.x;

    if (cta >= NCONS) {
        // ------------------------- PRODUCER -------------------------
        // Timestep s = cta - NCONS. Warp w owns rows w*32..w*32+31,
        // 4 rows per iteration: lane loads one float4 of each row
        // (coalesced 512B per row), dot4 vs weight slice, 5-level shfl
        // reduce (4 chains interleaved), lane0 STG.128s 4 results.
        const int s    = cta - NCONS;
        const int lane = threadIdx.x & 31;
        const int warp = threadIdx.x >> 5;

        const float bias = b_ih0[0] + b_hh0[0];
        const float4 wv = reinterpret_cast<const float4*>(w_ih0)[lane];
        const float4* __restrict__ x4 = reinterpret_cast<const float4*>(x);

        const int rowbase = warp * 32;                    // within timestep
        const float4* __restrict__ xs =
            x4 + (size_t)(s * B_SZ + rowbase) * 32 + lane;

        #pragma unroll
        for (int i = 0; i < 8; i++) {
            // rows rowbase+4i .. rowbase+4i+3
            float4 v0 = xs[(4 * i + 0) * 32];
            float4 v1 = xs[(4 * i + 1) * 32];
            float4 v2 = xs[(4 * i + 2) * 32];
            float4 v3 = xs[(4 * i + 3) * 32];

            float a0 = dot4(v0, wv);
            float a1_ = dot4(v1, wv);
            float a2 = dot4(v2, wv);
            float a3 = dot4(v3, wv);

            #pragma unroll
            for (int o = 16; o; o >>= 1) {
                a0  += __shfl_xor_sync(0xffffffffu, a0, o);
                a1_ += __shfl_xor_sync(0xffffffffu, a1_, o);
                a2  += __shfl_xor_sync(0xffffffffu, a2, o);
                a3  += __shfl_xor_sync(0xffffffffu, a3, o);
            }
            if (lane == 0) {
                float4 r = make_float4(a0 + bias, a1_ + bias,
                                       a2 + bias, a3 + bias);
                *reinterpret_cast<float4*>(&g_xp[s * B_SZ + rowbase + 4 * i]) = r;
            }
        }
        __syncthreads();                       // all 256 rows of s stored
        if (threadIdx.x == 0)
            red_release_inc(&g_cnt[s >> 4]);   // publish step s into its chunk
        return;
    }

    // ------------------------- CONSUMER -------------------------
    if (threadIdx.x >= 32) return;            // 1 warp per consumer CTA
    const int b = cta * 32 + threadIdx.x;     // 0..255

    const float w00 = w_hh0[0];
    const float a1  = w_ih1[0];
    const float d1  = w_hh1[0];
    const float c1  = b_ih1[0] + b_hh1[0];

    float h1 = 0.0f, h2 = 0.0f, sv = 0.0f;    // => pipelined h2_{-1}=0
    float buf[2][CHUNK];
    const float* __restrict__ xp = g_xp;

    // prologue: wait chunks 0 and 1, load them; preload counter for chunk 2
    {
        unsigned cv0 = ldrelax(&g_cnt[0]);
        while (cv0 < CHUNK) { __nanosleep(64); cv0 = ldrelax(&g_cnt[0]); }
        cv0 = ldrelax(&g_cnt[1]);
        while (cv0 < CHUNK) { __nanosleep(64); cv0 = ldrelax(&g_cnt[1]); }
        fence_acq();
        #pragma unroll
        for (int j = 0; j < CHUNK; j++) buf[0][j] = xp[j * B_SZ + b];
        #pragma unroll
        for (int j = 0; j < CHUNK; j++) buf[1][j] = xp[(CHUNK + j) * B_SZ + b];
    }
    unsigned cv = ldrelax(&g_cnt[2]);

    // main loop: iter c consumes chunk c from buf[c&1] and refills that buffer
    // with chunk c+2. One relaxed counter load + one fence per chunk.
    for (int c = 0; c < NCHUNK - 2; c++) {
        while (cv < CHUNK) { __nanosleep(32); cv = ldrelax(&g_cnt[c + 2]); }
        fence_acq();                            // order xp loads after observation

        const int p  = c & 1;
        const int sb = (c + 2) * CHUNK;
        #pragma unroll
        for (int j = 0; j < CHUNK; j++) {
            STEP(buf[p][j]);
            buf[p][j] = xp[(sb + j) * B_SZ + b];
        }
        cv = ldrelax(&g_cnt[c + 3]);            // pad covers c+3 == 128
    }

    // epilogue: chunk 126 (buf0), chunk 127 (buf1)
    #pragma unroll
    for (int j = 0; j < CHUNK; j++) STEP(buf[0][j]);
    #pragma unroll
    for (int j = 0; j < CHUNK; j++) STEP(buf[1][j]);

    h2 = tanh_fast(fmaf(h2, d1, sv));           // recover h2_{S-1}
    out[b] = 1.0f / (1.0f + __expf(-h2));

    // cleanup for graph replay: last consumer CTA zeroes counters.
    __syncwarp();
    unsigned last = 0;
    if (threadIdx.x == 0) {
        asm volatile("fence.acq_rel.gpu;" ::: "memory");
        last = (atomicAdd(&g_done, 1u) == NCONS - 1) ? 1u : 0u;
    }
    last = __shfl_sync(0xffffffffu, last, 0);
    if (last) {
        asm volatile("fence.acq_rel.gpu;" ::: "memory");
        for (int i = threadIdx.x; i < NCHUNK + 2; i += 32)
            g_cnt[i] = 0u;
        if (threadIdx.x == 0) g_done = 0u;
    }
}

extern "C" void kernel_launch(void* const* d_in, const int* in_sizes, int n_in,
                              void* d_out, int out_size)
{
    const float* x    = (const float*)d_in[0];
    const float* Wih0 = (const float*)d_in[1];
    const float* Whh0 = (const float*)d_in[2];
    const float* bih0 = (const float*)d_in[3];
    const float* bhh0 = (const float*)d_in[4];
    const float* Wih1 = (const float*)d_in[5];
    const float* Whh1 = (const float*)d_in[6];
    const float* bih1 = (const float*)d_in[7];
    const float* bhh1 = (const float*)d_in[8];
    float* out = (float*)d_out;

    rnn_fused<<<NCTA, 256>>>(x, Wih0, Whh0, bih0, bhh0,
                             Wih1, Whh1, bih1, bhh1, out);
}

// round 10
// speedup vs baseline: 1.0014x; 1.0014x over previous
#include <cuda_runtime.h>
#include <cuda_bf16.h>

// Fused 2-layer RNN (hidden=1), S=2048, B=256, I=128.
//   xp[s,b] = x[s,b,:].W_ih0 + b_ih0 + b_hh0          (producers, HBM stream)
//   h1 = tanh(xp + h1*Whh0); h2 = tanh(h1*Wih1 + b1 + h2*Whh1)  (consumers)
//   out[b] = sigmoid(h2[S-1,b])
//
// R7 = R6 resubmit (R6 hit an infra failure, never measured) + __nanosleep
// in consumer poll loops. Producer: R1-measured shape (warp-per-row,
// lane-per-float4, 5-level shfl) at 4 CTAs/SM, one timestep per CTA.
// Consumer + chunk-counter sync proven in R5.

#define S_LEN  2048
#define B_SZ   256
#define NCONS  8
#define NPROD  2048                      // one timestep per producer CTA
#define NCTA   (NCONS + NPROD)
#define CHUNK  16
#define NCHUNK (S_LEN / CHUNK)           // 128

__device__ float    g_xp[S_LEN * B_SZ];  // [s][b]
__device__ unsigned g_cnt[NCHUNK + 2];   // per-chunk completion counters (+pad)
__device__ unsigned g_done;

__device__ __forceinline__ float tanh_fast(float x) {
    float y;
    asm("tanh.approx.f32 %0, %1;" : "=f"(y) : "f"(x));
    return y;
}
__device__ __forceinline__ unsigned ldrelax(const unsigned* p) {
    unsigned v;
    asm volatile("ld.relaxed.gpu.global.u32 %0, [%1];" : "=r"(v) : "l"(p) : "memory");
    return v;
}
__device__ __forceinline__ void fence_acq() {
    asm volatile("fence.acq_rel.gpu;" ::: "memory");
}
__device__ __forceinline__ void red_release_inc(unsigned* p) {
    asm volatile("red.release.gpu.global.add.u32 [%0], 1;" :: "l"(p) : "memory");
}
__device__ __forceinline__ float dot4(float4 a, float4 b) {
    return fmaf(a.x, b.x, fmaf(a.y, b.y, fmaf(a.z, b.z, a.w * b.w)));
}

// Pipelined recurrence step: computes h1_j and h2_{j-1}; both FFMA issue
// before both MUFU so the two tanh cycles overlap. (Numerics proven R2/R4/R5.)
#define STEP(xv) do {                    \
    float p1_ = fmaf(h1, w00, (xv));     \
    float p2_ = fmaf(h2, d1, sv);        \
    h1 = tanh_fast(p1_);                 \
    h2 = tanh_fast(p2_);                 \
    sv = fmaf(h1, a1, c1);               \
} while (0)

__global__ __launch_bounds__(256, 4) void rnn_fused(
    const float* __restrict__ x,
    const float* __restrict__ w_ih0,
    const float* __restrict__ w_hh0,
    const float* __restrict__ b_ih0,
    const float* __restrict__ b_hh0,
    const float* __restrict__ w_ih1,
    const float* __restrict__ w_hh1,
    const float* __restrict__ b_ih1,
    const float* __restrict__ b_hh1,
    float* __restrict__ out)
{
    const int cta = blockIdx.x;

    if (cta >= NCONS) {
        // ------------------------- PRODUCER -------------------------
        // Timestep s = cta - NCONS. Warp w owns rows w*32..w*32+31,
        // 4 rows per iteration: lane loads one float4 of each row
        // (coalesced 512B per row), dot4 vs weight slice, 5-level shfl
        // reduce (4 chains interleaved), lane0 STG.128s 4 results.
        const int s    = cta - NCONS;
        const int lane = threadIdx.x & 31;
        const int warp = threadIdx.x >> 5;

        const float bias = b_ih0[0] + b_hh0[0];
        const float4 wv = reinterpret_cast<const float4*>(w_ih0)[lane];
        const float4* __restrict__ x4 = reinterpret_cast<const float4*>(x);

        const int rowbase = warp * 32;                    // within timestep
        const float4* __restrict__ xs =
            x4 + (size_t)(s * B_SZ + rowbase) * 32 + lane;

        #pragma unroll
        for (int i = 0; i < 8; i++) {
            // rows rowbase+4i .. rowbase+4i+3
            float4 v0 = xs[(4 * i + 0) * 32];
            float4 v1 = xs[(4 * i + 1) * 32];
            float4 v2 = xs[(4 * i + 2) * 32];
            float4 v3 = xs[(4 * i + 3) * 32];

            float a0 = dot4(v0, wv);
            float a1_ = dot4(v1, wv);
            float a2 = dot4(v2, wv);
            float a3 = dot4(v3, wv);

            #pragma unroll
            for (int o = 16; o; o >>= 1) {
                a0  += __shfl_xor_sync(0xffffffffu, a0, o);
                a1_ += __shfl_xor_sync(0xffffffffu, a1_, o);
                a2  += __shfl_xor_sync(0xffffffffu, a2, o);
                a3  += __shfl_xor_sync(0xffffffffu, a3, o);
            }
            if (lane == 0) {
                float4 r = make_float4(a0 + bias, a1_ + bias,
                                       a2 + bias, a3 + bias);
                *reinterpret_cast<float4*>(&g_xp[s * B_SZ + rowbase + 4 * i]) = r;
            }
        }
        __syncthreads();                       // all 256 rows of s stored
        if (threadIdx.x == 0)
            red_release_inc(&g_cnt[s >> 4]);   // publish step s into its chunk
        return;
    }

    // ------------------------- CONSUMER -------------------------
    if (threadIdx.x >= 32) return;            // 1 warp per consumer CTA
    const int b = cta * 32 + threadIdx.x;     // 0..255

    const float w00 = w_hh0[0];
    const float a1  = w_ih1[0];
    const float d1  = w_hh1[0];
    const float c1  = b_ih1[0] + b_hh1[0];

    float h1 = 0.0f, h2 = 0.0f, sv = 0.0f;    // => pipelined h2_{-1}=0
    float buf[2][CHUNK];
    const float* __restrict__ xp = g_xp;

    // prologue: wait chunks 0 and 1, load them; preload counter for chunk 2
    {
        unsigned cv0 = ldrelax(&g_cnt[0]);
        while (cv0 < CHUNK) { __nanosleep(64); cv0 = ldrelax(&g_cnt[0]); }
        cv0 = ldrelax(&g_cnt[1]);
        while (cv0 < CHUNK) { __nanosleep(64); cv0 = ldrelax(&g_cnt[1]); }
        fence_acq();
        #pragma unroll
        for (int j = 0; j < CHUNK; j++) buf[0][j] = xp[j * B_SZ + b];
        #pragma unroll
        for (int j = 0; j < CHUNK; j++) buf[1][j] = xp[(CHUNK + j) * B_SZ + b];
    }
    unsigned cv = ldrelax(&g_cnt[2]);

    // main loop: iter c consumes chunk c from buf[c&1] and refills that buffer
    // with chunk c+2. One relaxed counter load + one fence per chunk.
    for (int c = 0; c < NCHUNK - 2; c++) {
        while (cv < CHUNK) { __nanosleep(32); cv = ldrelax(&g_cnt[c + 2]); }
        fence_acq();                            // order xp loads after observation

        const int p  = c & 1;
        const int sb = (c + 2) * CHUNK;
        #pragma unroll
        for (int j = 0; j < CHUNK; j++) {
            STEP(buf[p][j]);
            buf[p][j] = xp[(sb + j) * B_SZ + b];
        }
        cv = ldrelax(&g_cnt[c + 3]);            // pad covers c+3 == 128
    }

    // epilogue: chunk 126 (buf0), chunk 127 (buf1)
    #pragma unroll
    for (int j = 0; j < CHUNK; j++) STEP(buf[0][j]);
    #pragma unroll
    for (int j = 0; j < CHUNK; j++) STEP(buf[1][j]);

    h2 = tanh_fast(fmaf(h2, d1, sv));           // recover h2_{S-1}
    out[b] = 1.0f / (1.0f + __expf(-h2));

    // cleanup for graph replay: last consumer CTA zeroes counters.
    __syncwarp();
    unsigned last = 0;
    if (threadIdx.x == 0) {
        asm volatile("fence.acq_rel.gpu;" ::: "memory");
        last = (atomicAdd(&g_done, 1u) == NCONS - 1) ? 1u : 0u;
    }
    last = __shfl_sync(0xffffffffu, last, 0);
    if (last) {
        asm volatile("fence.acq_rel.gpu;" ::: "memory");
        for (int i = threadIdx.x; i < NCHUNK + 2; i += 32)
            g_cnt[i] = 0u;
        if (threadIdx.x == 0) g_done = 0u;
    }
}

extern "C" void kernel_launch(void* const* d_in, const int* in_sizes, int n_in,
                              void* d_out, int out_size)
{
    const float* x    = (const float*)d_in[0];
    const float* Wih0 = (const float*)d_in[1];
    const float* Whh0 = (const float*)d_in[2];
    const float* bih0 = (const float*)d_in[3];
    const float* bhh0 = (const float*)d_in[4];
    const float* Wih1 = (const float*)d_in[5];
    const float* Whh1 = (const float*)d_in[6];
    const float* bih1 = (const float*)d_in[7];
    const float* bhh1 = (const float*)d_in[8];
    float* out = (float*)d_out;

    rnn_fused<<<NCTA, 256>>>(x, Wih0, Whh0, bih0, bhh0,
                             Wih1, Whh1, bih1, bhh1, out);
}